// round 11
// baseline (speedup 1.0000x reference)
#include <cuda_runtime.h>
#include <math.h>

#define NB_MAX 296

__device__ __align__(16) float g_Acoef[81 * 4];
__device__ __align__(16) float g_part[NB_MAX * 8];
__device__ __align__(16) float g_norm[8];
__device__ int g_ticket;                 // monotonic across launches
__device__ int g_arrive;                 // monotonic across launches
__device__ volatile int g_acoef_flag;    // released as gen+1
__device__ volatile int g_norm_flag;     // released as gen+1

__device__ __forceinline__ float pick_phase(int ph, float hr, float hi)
{
    return (ph == 0) ? hr : (ph == 1) ? -hi : (ph == 2) ? -hr : hi;
}

__device__ __forceinline__ void circuit_eval(const float4* __restrict__ As,
                                             float a0, float a1, float a2, float a3,
                                             float& q0, float& q1, float& q2, float& q3)
{
    const float inv = 1.f / 36.f;
    float c0, s0, c1, s1, c2, s2, c3, s3;
    __sincosf(a0 * inv, &s0, &c0);
    __sincosf(a1 * inv, &s1, &c1);
    __sincosf(a2 * inv, &s2, &c2);
    __sincosf(a3 * inv, &s3, &c3);
    float t01[9] = { 1.f, c1, s1, c0, c0 * c1, c0 * s1, s0, s0 * c1, s0 * s1 };
    float t23[9] = { 1.f, c3, s3, c2, c2 * c3, c2 * s3, s2, s2 * c3, s2 * s3 };
#pragma unroll
    for (int m = 0; m < 81; m++) {
        float bs = t01[m / 9] * t23[m % 9];
        float4 a = As[m];
        q0 = fmaf(a.x, bs, q0);
        q1 = fmaf(a.y, bs, q1);
        q2 = fmaf(a.z, bs, q2);
        q3 = fmaf(a.w, bs, q3);
    }
}

__device__ __forceinline__ void ldg_chunk(const float4* __restrict__ x4, long base,
                                          long totalF4, int lane, float* sx, float* sz)
{
#pragma unroll
    for (int k = 0; k < 9; k++) {
        long gi = base + lane + k * 32;
        float4 v = make_float4(0.f, 0.f, 0.f, 0.f);
        if (gi < totalF4) v = x4[gi];
        sx[k] = v.x + v.y;
        sz[k] = v.z + v.w;
    }
}

__device__ __forceinline__ void sts_chunk(float2* buf, int lane,
                                          const float* sx, const float* sz)
{
#pragma unroll
    for (int k = 0; k < 9; k++)
        buf[lane + k * 32] = make_float2(sx[k], sz[k]);
}

__device__ __forceinline__ void pool_chunk(const float2* buf, int rdBase, int srcLane,
                                           float& b0, float& b1, float& b2, float& b3)
{
    float r0 = 0.f, r1 = 0.f;
#pragma unroll
    for (int i = 0; i < 9; i++) {
        float2 v = buf[rdBase + i];
        if (i % 3 == 0)      r0 += v.x + v.y;
        else if (i % 3 == 1) { r0 += v.x; r1 += v.y; }
        else                 r1 += v.x + v.y;
    }
    r0 += __shfl_xor_sync(0xffffffffu, r0, 1);
    r1 += __shfl_xor_sync(0xffffffffu, r1, 1);
    float r2 = __shfl_xor_sync(0xffffffffu, r0, 2);
    float r3 = __shfl_xor_sync(0xffffffffu, r1, 2);
    b0 = __shfl_sync(0xffffffffu, r0, srcLane);
    b1 = __shfl_sync(0xffffffffu, r1, srcLane);
    b2 = __shfl_sync(0xffffffffu, r2, srcLane);
    b3 = __shfl_sync(0xffffffffu, r3, srcLane);
}

// ---------------------------------------------------------------------------
// Single fused kernel: setup(block0) + warp-autonomous pooling + circuit +
// mean/var + norm + out.  No __syncthreads in the pooling hot loop.
// Item layout: warp w of a tile owns items [w*32, w*32+32); a lane's item
// after pooling is  itemLocal = w*32 + lane.
// ---------------------------------------------------------------------------
__global__ __launch_bounds__(256, 2)
void fused_kernel(const float* __restrict__ x,
                  const float* __restrict__ W,
                  const float* __restrict__ gamma,
                  const float* __restrict__ beta,
                  float* __restrict__ out,
                  int B, int nb, int nChunks)
{
    __shared__ float2 wbuf[8][2][288];    // per-warp double buffers, 36,864 B
    __shared__ float4 As[81];
    __shared__ float wsum[8][8];
    __shared__ int shGen;
    __shared__ int shLast;
    __shared__ union {
        struct {
            float CS[24][2];
            float Mre[16][16];
            float Mim[16][16];
            float G[4][16][16];
        } su;
        struct {
            double red[8][32];
            double tot[8];
        } ru;
    } U;

    int tid = threadIdx.x;
    int lane = tid & 31;
    int w = tid >> 5;

    if (tid == 0) shGen = atomicAdd(&g_ticket, 1) / nb;
    __syncthreads();
    int gen = shGen;

    // ---- Block 0: build the 4x81 coefficient table (lane-parallel) ----
    if (blockIdx.x == 0) {
        if (tid < 24) {
            float c, s;
            __sincosf(W[tid] * 0.5f, &s, &c);
            U.su.CS[tid][0] = c;
            U.su.CS[tid][1] = s;
        }
        __syncthreads();
        {
            int i = lane & 15;
            int jl = lane >> 4;
            int j = w * 2 + jl;
            float re = (i == j) ? 1.f : 0.f;
            float im = 0.f;
#pragma unroll
            for (int l = 0; l < 2; l++) {
#pragma unroll
                for (int g2 = 0; g2 < 4; g2++) {
                    int gi = (l * 4 + g2) * 3;
                    const int m = 1 << (3 - g2);
                    float c, s, pre, pim;
                    c = U.su.CS[gi + 0][0]; s = U.su.CS[gi + 0][1];
                    pre = __shfl_xor_sync(0xffffffffu, re, m);
                    pim = __shfl_xor_sync(0xffffffffu, im, m);
                    {
                        float nr = fmaf(s, pim, c * re);
                        float ni = fmaf(-s, pre, c * im);
                        re = nr; im = ni;
                    }
                    c = U.su.CS[gi + 1][0]; s = U.su.CS[gi + 1][1];
                    pre = __shfl_xor_sync(0xffffffffu, re, m);
                    pim = __shfl_xor_sync(0xffffffffu, im, m);
                    {
                        float sg = (i & m) ? s : -s;
                        float nr = fmaf(sg, pre, c * re);
                        float ni = fmaf(sg, pim, c * im);
                        re = nr; im = ni;
                    }
                    c = U.su.CS[gi + 2][0]; s = U.su.CS[gi + 2][1];
                    {
                        float tt = (i & m) ? -s : s;
                        float nr = fmaf(tt, im, c * re);
                        float ni = fmaf(-tt, re, c * im);
                        re = nr; im = ni;
                    }
                }
#pragma unroll
                for (int g2 = 0; g2 < 4; g2++) {
                    int t2 = (g2 + 1) & 3;
                    int cm = 1 << (3 - g2), tm = 1 << (3 - t2);
                    int src = (((i & cm) ? (i ^ tm) : i) | (jl << 4));
                    re = __shfl_sync(0xffffffffu, re, src);
                    im = __shfl_sync(0xffffffffu, im, src);
                }
            }
            U.su.Mre[i][j] = re;
            U.su.Mim[i][j] = im;
        }
        __syncthreads();
        {
            int j2 = tid >> 4, k2 = tid & 15;
            float hr0 = 0, hr1 = 0, hr2 = 0, hr3 = 0;
            float hi0 = 0, hi1 = 0, hi2 = 0, hi3 = 0;
#pragma unroll
            for (int i2 = 0; i2 < 16; i2++) {
                float ar = U.su.Mre[i2][j2], ai = U.su.Mim[i2][j2];
                float br = U.su.Mre[i2][k2], bi = U.su.Mim[i2][k2];
                float tr = ar * br + ai * bi;
                float ti = ar * bi - ai * br;
                if (i2 & 8) { hr0 -= tr; hi0 -= ti; } else { hr0 += tr; hi0 += ti; }
                if (i2 & 4) { hr1 -= tr; hi1 -= ti; } else { hr1 += tr; hi1 += ti; }
                if (i2 & 2) { hr2 -= tr; hi2 -= ti; } else { hr2 += tr; hi2 += ti; }
                if (i2 & 1) { hr3 -= tr; hi3 -= ti; } else { hr3 += tr; hi3 += ti; }
            }
            int ph = (__popc(j2) - __popc(k2)) & 3;
            U.su.G[0][j2][k2] = pick_phase(ph, hr0, hi0);
            U.su.G[1][j2][k2] = pick_phase(ph, hr1, hi1);
            U.su.G[2][j2][k2] = pick_phase(ph, hr2, hi2);
            U.su.G[3][j2][k2] = pick_phase(ph, hr3, hi3);
        }
        __syncthreads();
        for (int idx = tid; idx < 324; idx += 256) {
            int ow = idx / 81;
            int m = idx % 81;
            int md[4] = { m / 27, (m / 9) % 3, (m / 3) % 3, m % 3 };
            float acc = 0.f;
#pragma unroll
            for (int t = 0; t < 16; t++) {
                int jj = 0, kk = 0;
                float sgn = 1.f;
#pragma unroll
                for (int w2 = 0; w2 < 4; w2++) {
                    int tb = (t >> (3 - w2)) & 1;
                    int jb, kb;
                    if (md[w2] == 2) { jb = tb; kb = 1 - tb; }
                    else { jb = tb; kb = tb; if (md[w2] == 1 && tb == 1) sgn = -sgn; }
                    jj |= jb << (3 - w2);
                    kk |= kb << (3 - w2);
                }
                acc += sgn * U.su.G[ow][jj][kk];
            }
            g_Acoef[m * 4 + ow] = acc * (1.f / 16.f);
        }
        __threadfence();
        __syncthreads();
        if (tid == 0) g_acoef_flag = gen + 1;
    }

    // ---- Tile assignment: block 0 gets lightest load ----
    int tiles0 = blockIdx.x;
    int rev = nb - 1 - blockIdx.x;
    int tiles1 = (nb + rev < nChunks) ? (nb + rev) : -1;
    int nt = (tiles1 >= 0) ? 2 : 1;

    // ---- Warp-autonomous pooling (no block barriers) ----
    const float4* x4 = (const float4*)x;
    long totalF4 = (long)B * 36;
    int rdBase = (lane >> 2) * 36 + (lane & 3) * 9;
    int myT = lane >> 3;
    int srcLane = (lane & 7) * 4;

    float2* buf0 = &wbuf[w][0][0];
    float2* buf1 = &wbuf[w][1][0];

    float A00 = 0, A01 = 0, A02 = 0, A03 = 0;
    float A10 = 0, A11 = 0, A12 = 0, A13 = 0;
    float sxA[9], szA[9], sxB[9], szB[9];

    int totalSub = nt * 4;
    // chunk s covers items tile*256 + w*32 + (s&3)*8 .. +8
    long wOff = (long)w * 1152;
    long base0 = (long)tiles0 * 9216 + wOff;
    long base1 = (nt == 2) ? ((long)tiles1 * 9216 + wOff) : 0;

    ldg_chunk(x4, base0, totalF4, lane, sxA, szA);   // chunk 0 -> A

#pragma unroll
    for (int s = 0; s < 8; s += 2) {
        if (s >= totalSub) break;
        // even iteration: staged A -> slot 0
        sts_chunk(buf0, lane, sxA, szA);
        if (s + 1 < totalSub) {
            long nbase = ((s + 1) >= 4 ? base1 : base0) + ((s + 1) & 3) * 288;
            ldg_chunk(x4, nbase, totalF4, lane, sxB, szB);
        }
        __syncwarp();
        {
            float b0, b1, b2, b3;
            pool_chunk(buf0, rdBase, srcLane, b0, b1, b2, b3);
            bool mine = (myT == (s & 3));
            if (s < 4) {
                A00 = mine ? b0 : A00;  A01 = mine ? b1 : A01;
                A02 = mine ? b2 : A02;  A03 = mine ? b3 : A03;
            } else {
                A10 = mine ? b0 : A10;  A11 = mine ? b1 : A11;
                A12 = mine ? b2 : A12;  A13 = mine ? b3 : A13;
            }
        }
        // odd iteration: staged B -> slot 1
        if (s + 1 < totalSub) {
            sts_chunk(buf1, lane, sxB, szB);
            if (s + 2 < totalSub) {
                long nbase = ((s + 2) >= 4 ? base1 : base0) + ((s + 2) & 3) * 288;
                ldg_chunk(x4, nbase, totalF4, lane, sxA, szA);
            }
            __syncwarp();
            float b0, b1, b2, b3;
            pool_chunk(buf1, rdBase, srcLane, b0, b1, b2, b3);
            bool mine = (myT == ((s + 1) & 3));
            if (s + 1 < 4) {
                A00 = mine ? b0 : A00;  A01 = mine ? b1 : A01;
                A02 = mine ? b2 : A02;  A03 = mine ? b3 : A03;
            } else {
                A10 = mine ? b0 : A10;  A11 = mine ? b1 : A11;
                A12 = mine ? b2 : A12;  A13 = mine ? b3 : A13;
            }
        }
    }

    // ---- Wait for coefficients, load As ----
    if (blockIdx.x != 0) {
        if (tid == 0) {
            while (g_acoef_flag < gen + 1) __nanosleep(32);
        }
        __syncthreads();
        __threadfence();
    }
    if (tid < 81) As[tid] = __ldcg(((const float4*)g_Acoef) + tid);
    __syncthreads();

    // ---- Circuit (register-resident) + partial sums ----
    // FIXED: a lane's pooled item under the warp-autonomous layout is
    // itemLocal = w*32 + lane  (warp w owns items [w*32, w*32+32)).
    int itemLocal = w * 32 + lane;
    float q00 = 0, q01 = 0, q02 = 0, q03 = 0;
    float q10 = 0, q11 = 0, q12 = 0, q13 = 0;
    {
        int item = tiles0 * 256 + itemLocal;
        if (item < B) circuit_eval(As, A00, A01, A02, A03, q00, q01, q02, q03);
    }
    if (nt == 2) {
        int item = tiles1 * 256 + itemLocal;
        if (item < B) circuit_eval(As, A10, A11, A12, A13, q10, q11, q12, q13);
    }

    float s8[8] = { q00 + q10, q01 + q11, q02 + q12, q03 + q13,
                    q00 * q00 + q10 * q10, q01 * q01 + q11 * q11,
                    q02 * q02 + q12 * q12, q03 * q03 + q13 * q13 };
#pragma unroll
    for (int sh = 16; sh; sh >>= 1)
#pragma unroll
        for (int k = 0; k < 8; k++) s8[k] += __shfl_xor_sync(0xffffffffu, s8[k], sh);
    if (lane == 0) {
#pragma unroll
        for (int k = 0; k < 8; k++) wsum[w][k] = s8[k];
    }
    __syncthreads();
    if (tid < 8) {
        float acc = 0.f;
#pragma unroll
        for (int ww = 0; ww < 8; ww++) acc += wsum[ww][tid];
        g_part[blockIdx.x * 8 + tid] = acc;
        __threadfence();
    }
    __syncthreads();

    // ---- Arrival; last block computes norm params ----
    if (tid == 0) {
        int pos = atomicAdd(&g_arrive, 1);
        shLast = ((pos % nb) == nb - 1);
    }
    __syncthreads();

    if (shLast) {
        __threadfence();
        int k = tid & 7;
        int slice = tid >> 3;
        double acc = 0.0;
        for (int b = slice; b < nb; b += 32)
            acc += (double)g_part[b * 8 + k];
        U.ru.red[k][slice] = acc;
        __syncthreads();
        if (tid < 8) {
            double t = 0.0;
#pragma unroll
            for (int i = 0; i < 32; i++) t += U.ru.red[tid][i];
            U.ru.tot[tid] = t;
        }
        __syncthreads();
        if (tid < 4) {
            double mean = U.ru.tot[tid] / (double)B;
            double var = U.ru.tot[4 + tid] / (double)B - mean * mean;
            float scale = gamma[tid] * rsqrtf((float)var + 1e-5f);
            g_norm[tid] = scale;
            g_norm[4 + tid] = beta[tid] - (float)mean * scale;
            __threadfence();
        }
        __syncthreads();
        if (tid == 0) g_norm_flag = gen + 1;
    }

    // ---- Wait for norm params, apply to register q, write out ----
    if (tid == 0) {
        while (g_norm_flag < gen + 1) __nanosleep(32);
    }
    __syncthreads();
    __threadfence();

    float sc0 = __ldcg(&g_norm[0]), sc1 = __ldcg(&g_norm[1]);
    float sc2 = __ldcg(&g_norm[2]), sc3 = __ldcg(&g_norm[3]);
    float bs0 = __ldcg(&g_norm[4]), bs1 = __ldcg(&g_norm[5]);
    float bs2 = __ldcg(&g_norm[6]), bs3 = __ldcg(&g_norm[7]);

    {
        int item = tiles0 * 256 + itemLocal;
        if (item < B) {
            float4 o;
            o.x = fmaf(q00, sc0, bs0);
            o.y = fmaf(q01, sc1, bs1);
            o.z = fmaf(q02, sc2, bs2);
            o.w = fmaf(q03, sc3, bs3);
            ((float4*)out)[item] = o;
        }
    }
    if (nt == 2) {
        int item = tiles1 * 256 + itemLocal;
        if (item < B) {
            float4 o;
            o.x = fmaf(q10, sc0, bs0);
            o.y = fmaf(q11, sc1, bs1);
            o.z = fmaf(q12, sc2, bs2);
            o.w = fmaf(q13, sc3, bs3);
            ((float4*)out)[item] = o;
        }
    }
}

// ---------------------------------------------------------------------------
extern "C" void kernel_launch(void* const* d_in, const int* in_sizes, int n_in,
                              void* d_out, int out_size)
{
    const float* x     = (const float*)d_in[0];
    const float* W     = (const float*)d_in[1];
    const float* gamma = (const float*)d_in[2];
    const float* beta  = (const float*)d_in[3];
    float* out = (float*)d_out;

    int B = in_sizes[0] / 144;
    int nChunks = (B + 255) / 256;
    int nb = (nChunks < NB_MAX) ? nChunks : NB_MAX;

    fused_kernel<<<nb, 256>>>(x, W, gamma, beta, out, B, nb, nChunks);
}

// round 13
// speedup vs baseline: 1.0011x; 1.0011x over previous
#include <cuda_runtime.h>
#include <math.h>

#define NB_MAX 296

__device__ __align__(16) float g_Acoef[81 * 4];
__device__ __align__(16) float g_part[NB_MAX * 8];
__device__ __align__(16) float g_norm[8];
__device__ int g_ticket;                 // monotonic across launches
__device__ int g_arrive;                 // monotonic across launches
__device__ volatile int g_acoef_flag;    // released as gen+1
__device__ volatile int g_norm_flag;     // released as gen+1

__device__ __forceinline__ float pick_phase(int ph, float hr, float hi)
{
    return (ph == 0) ? hr : (ph == 1) ? -hi : (ph == 2) ? -hr : hi;
}

__device__ __forceinline__ void circuit_eval(const float4* __restrict__ As,
                                             float a0, float a1, float a2, float a3,
                                             float& q0, float& q1, float& q2, float& q3)
{
    const float inv = 1.f / 36.f;
    float c0, s0, c1, s1, c2, s2, c3, s3;
    __sincosf(a0 * inv, &s0, &c0);
    __sincosf(a1 * inv, &s1, &c1);
    __sincosf(a2 * inv, &s2, &c2);
    __sincosf(a3 * inv, &s3, &c3);
    float t01[9] = { 1.f, c1, s1, c0, c0 * c1, c0 * s1, s0, s0 * c1, s0 * s1 };
    float t23[9] = { 1.f, c3, s3, c2, c2 * c3, c2 * s3, s2, s2 * c3, s2 * s3 };
#pragma unroll
    for (int m = 0; m < 81; m++) {
        float bs = t01[m / 9] * t23[m % 9];
        float4 a = As[m];
        q0 = fmaf(a.x, bs, q0);
        q1 = fmaf(a.y, bs, q1);
        q2 = fmaf(a.z, bs, q2);
        q3 = fmaf(a.w, bs, q3);
    }
}

__device__ __forceinline__ void ldg_chunk(const float4* __restrict__ x4, long base,
                                          long totalF4, int lane, float* sx, float* sz)
{
#pragma unroll
    for (int k = 0; k < 9; k++) {
        long gi = base + lane + k * 32;
        float4 v = make_float4(0.f, 0.f, 0.f, 0.f);
        if (gi < totalF4) v = x4[gi];
        sx[k] = v.x + v.y;
        sz[k] = v.z + v.w;
    }
}

__device__ __forceinline__ void sts_chunk(float2* buf, int lane,
                                          const float* sx, const float* sz)
{
#pragma unroll
    for (int k = 0; k < 9; k++)
        buf[lane + k * 32] = make_float2(sx[k], sz[k]);
}

__device__ __forceinline__ void pool_chunk(const float2* buf, int rdBase, int srcLane,
                                           float& b0, float& b1, float& b2, float& b3)
{
    float r0 = 0.f, r1 = 0.f;
#pragma unroll
    for (int i = 0; i < 9; i++) {
        float2 v = buf[rdBase + i];
        if (i % 3 == 0)      r0 += v.x + v.y;
        else if (i % 3 == 1) { r0 += v.x; r1 += v.y; }
        else                 r1 += v.x + v.y;
    }
    r0 += __shfl_xor_sync(0xffffffffu, r0, 1);
    r1 += __shfl_xor_sync(0xffffffffu, r1, 1);
    float r2 = __shfl_xor_sync(0xffffffffu, r0, 2);
    float r3 = __shfl_xor_sync(0xffffffffu, r1, 2);
    b0 = __shfl_sync(0xffffffffu, r0, srcLane);
    b1 = __shfl_sync(0xffffffffu, r1, srcLane);
    b2 = __shfl_sync(0xffffffffu, r2, srcLane);
    b3 = __shfl_sync(0xffffffffu, r3, srcLane);
}

// ---------------------------------------------------------------------------
// Single fused kernel: setup(block0) + warp-autonomous pooling with a 2-deep
// load pipeline (chunk s+2's LDGs issued while chunk s is processed, so
// consecutive chunk loads overlap) + circuit + mean/var + norm + out.
// Item layout: warp w of a tile owns items [w*32, w*32+32);
// a lane's item after pooling is itemLocal = w*32 + lane.
// ---------------------------------------------------------------------------
__global__ __launch_bounds__(256, 2)
void fused_kernel(const float* __restrict__ x,
                  const float* __restrict__ W,
                  const float* __restrict__ gamma,
                  const float* __restrict__ beta,
                  float* __restrict__ out,
                  int B, int nb, int nChunks)
{
    __shared__ float2 wbuf[8][2][288];    // per-warp double buffers, 36,864 B
    __shared__ float4 As[81];
    __shared__ float wsum[8][8];
    __shared__ int shGen;
    __shared__ int shLast;
    __shared__ union {
        struct {
            float CS[24][2];
            float Mre[16][16];
            float Mim[16][16];
            float G[4][16][16];
        } su;
        struct {
            double red[8][32];
            double tot[8];
        } ru;
    } U;

    int tid = threadIdx.x;
    int lane = tid & 31;
    int w = tid >> 5;

    if (tid == 0) shGen = atomicAdd(&g_ticket, 1) / nb;
    __syncthreads();
    int gen = shGen;

    // ---- Block 0: build the 4x81 coefficient table (lane-parallel) ----
    if (blockIdx.x == 0) {
        if (tid < 24) {
            float c, s;
            __sincosf(W[tid] * 0.5f, &s, &c);
            U.su.CS[tid][0] = c;
            U.su.CS[tid][1] = s;
        }
        __syncthreads();
        {
            int i = lane & 15;
            int jl = lane >> 4;
            int j = w * 2 + jl;
            float re = (i == j) ? 1.f : 0.f;
            float im = 0.f;
#pragma unroll
            for (int l = 0; l < 2; l++) {
#pragma unroll
                for (int g2 = 0; g2 < 4; g2++) {
                    int gi = (l * 4 + g2) * 3;
                    const int m = 1 << (3 - g2);
                    float c, s, pre, pim;
                    c = U.su.CS[gi + 0][0]; s = U.su.CS[gi + 0][1];
                    pre = __shfl_xor_sync(0xffffffffu, re, m);
                    pim = __shfl_xor_sync(0xffffffffu, im, m);
                    {
                        float nr = fmaf(s, pim, c * re);
                        float ni = fmaf(-s, pre, c * im);
                        re = nr; im = ni;
                    }
                    c = U.su.CS[gi + 1][0]; s = U.su.CS[gi + 1][1];
                    pre = __shfl_xor_sync(0xffffffffu, re, m);
                    pim = __shfl_xor_sync(0xffffffffu, im, m);
                    {
                        float sg = (i & m) ? s : -s;
                        float nr = fmaf(sg, pre, c * re);
                        float ni = fmaf(sg, pim, c * im);
                        re = nr; im = ni;
                    }
                    c = U.su.CS[gi + 2][0]; s = U.su.CS[gi + 2][1];
                    {
                        float tt = (i & m) ? -s : s;
                        float nr = fmaf(tt, im, c * re);
                        float ni = fmaf(-tt, re, c * im);
                        re = nr; im = ni;
                    }
                }
#pragma unroll
                for (int g2 = 0; g2 < 4; g2++) {
                    int t2 = (g2 + 1) & 3;
                    int cm = 1 << (3 - g2), tm = 1 << (3 - t2);
                    int src = (((i & cm) ? (i ^ tm) : i) | (jl << 4));
                    re = __shfl_sync(0xffffffffu, re, src);
                    im = __shfl_sync(0xffffffffu, im, src);
                }
            }
            U.su.Mre[i][j] = re;
            U.su.Mim[i][j] = im;
        }
        __syncthreads();
        {
            int j2 = tid >> 4, k2 = tid & 15;
            float hr0 = 0, hr1 = 0, hr2 = 0, hr3 = 0;
            float hi0 = 0, hi1 = 0, hi2 = 0, hi3 = 0;
#pragma unroll
            for (int i2 = 0; i2 < 16; i2++) {
                float ar = U.su.Mre[i2][j2], ai = U.su.Mim[i2][j2];
                float br = U.su.Mre[i2][k2], bi = U.su.Mim[i2][k2];
                float tr = ar * br + ai * bi;
                float ti = ar * bi - ai * br;
                if (i2 & 8) { hr0 -= tr; hi0 -= ti; } else { hr0 += tr; hi0 += ti; }
                if (i2 & 4) { hr1 -= tr; hi1 -= ti; } else { hr1 += tr; hi1 += ti; }
                if (i2 & 2) { hr2 -= tr; hi2 -= ti; } else { hr2 += tr; hi2 += ti; }
                if (i2 & 1) { hr3 -= tr; hi3 -= ti; } else { hr3 += tr; hi3 += ti; }
            }
            int ph = (__popc(j2) - __popc(k2)) & 3;
            U.su.G[0][j2][k2] = pick_phase(ph, hr0, hi0);
            U.su.G[1][j2][k2] = pick_phase(ph, hr1, hi1);
            U.su.G[2][j2][k2] = pick_phase(ph, hr2, hi2);
            U.su.G[3][j2][k2] = pick_phase(ph, hr3, hi3);
        }
        __syncthreads();
        for (int idx = tid; idx < 324; idx += 256) {
            int ow = idx / 81;
            int m = idx % 81;
            int md[4] = { m / 27, (m / 9) % 3, (m / 3) % 3, m % 3 };
            float acc = 0.f;
#pragma unroll
            for (int t = 0; t < 16; t++) {
                int jj = 0, kk = 0;
                float sgn = 1.f;
#pragma unroll
                for (int w2 = 0; w2 < 4; w2++) {
                    int tb = (t >> (3 - w2)) & 1;
                    int jb, kb;
                    if (md[w2] == 2) { jb = tb; kb = 1 - tb; }
                    else { jb = tb; kb = tb; if (md[w2] == 1 && tb == 1) sgn = -sgn; }
                    jj |= jb << (3 - w2);
                    kk |= kb << (3 - w2);
                }
                acc += sgn * U.su.G[ow][jj][kk];
            }
            g_Acoef[m * 4 + ow] = acc * (1.f / 16.f);
        }
        __threadfence();
        __syncthreads();
        if (tid == 0) g_acoef_flag = gen + 1;
    }

    // ---- Balanced tile assignment; block 0 gets 1 tile (absorbs setup) ----
    int tiles0 = blockIdx.x;
    int t1cand = nb - 1 + blockIdx.x;
    int tiles1 = (blockIdx.x != 0 && t1cand < nChunks) ? t1cand : -1;
    int nt = (tiles1 >= 0) ? 2 : 1;

    // ---- Warp-autonomous pooling with 2-deep load pipeline ----
    const float4* x4 = (const float4*)x;
    long totalF4 = (long)B * 36;
    int rdBase = (lane >> 2) * 36 + (lane & 3) * 9;
    int myT = lane >> 3;
    int srcLane = (lane & 7) * 4;

    float A00 = 0, A01 = 0, A02 = 0, A03 = 0;
    float A10 = 0, A11 = 0, A12 = 0, A13 = 0;
    float sxR[2][9], szR[2][9];

    int totalSub = nt * 4;
    long wOff = (long)w * 1152;
    long base0 = (long)tiles0 * 9216 + wOff;
    long base1 = (nt == 2) ? ((long)tiles1 * 9216 + wOff) : 0;

    // chunk s base address (s is compile-time under full unroll)
#define CBASE(s) ((((s) >= 4) ? base1 : base0) + ((s) & 3) * 288)

    // Prologue: issue chunks 0 and 1.
    ldg_chunk(x4, CBASE(0), totalF4, lane, sxR[0], szR[0]);
    if (totalSub > 1) ldg_chunk(x4, CBASE(1), totalF4, lane, sxR[1], szR[1]);

#pragma unroll
    for (int s = 0; s < 8; s++) {
        if (s >= totalSub) break;
        int slot = s & 1;
        // Store chunk s (waits only on chunk s's loads; s+1 stays in flight).
        sts_chunk(&wbuf[w][slot][0], lane, sxR[slot], szR[slot]);
        // Refill the slot with chunk s+2's loads (overlap with processing).
        if (s + 2 < totalSub)
            ldg_chunk(x4, CBASE(s + 2), totalF4, lane, sxR[slot], szR[slot]);
        __syncwarp();
        float b0, b1, b2, b3;
        pool_chunk(&wbuf[w][slot][0], rdBase, srcLane, b0, b1, b2, b3);
        bool mine = (myT == (s & 3));
        if (s < 4) {
            A00 = mine ? b0 : A00;  A01 = mine ? b1 : A01;
            A02 = mine ? b2 : A02;  A03 = mine ? b3 : A03;
        } else {
            A10 = mine ? b0 : A10;  A11 = mine ? b1 : A11;
            A12 = mine ? b2 : A12;  A13 = mine ? b3 : A13;
        }
    }
#undef CBASE

    // ---- Wait for coefficients, load As ----
    if (blockIdx.x != 0) {
        if (tid == 0) {
            while (g_acoef_flag < gen + 1) __nanosleep(32);
        }
        __syncthreads();
        __threadfence();
    }
    if (tid < 81) As[tid] = __ldcg(((const float4*)g_Acoef) + tid);
    __syncthreads();

    // ---- Circuit (register-resident) + partial sums ----
    int itemLocal = w * 32 + lane;
    float q00 = 0, q01 = 0, q02 = 0, q03 = 0;
    float q10 = 0, q11 = 0, q12 = 0, q13 = 0;
    {
        int item = tiles0 * 256 + itemLocal;
        if (item < B) circuit_eval(As, A00, A01, A02, A03, q00, q01, q02, q03);
    }
    if (nt == 2) {
        int item = tiles1 * 256 + itemLocal;
        if (item < B) circuit_eval(As, A10, A11, A12, A13, q10, q11, q12, q13);
    }

    float s8[8] = { q00 + q10, q01 + q11, q02 + q12, q03 + q13,
                    q00 * q00 + q10 * q10, q01 * q01 + q11 * q11,
                    q02 * q02 + q12 * q12, q03 * q03 + q13 * q13 };
#pragma unroll
    for (int sh = 16; sh; sh >>= 1)
#pragma unroll
        for (int k = 0; k < 8; k++) s8[k] += __shfl_xor_sync(0xffffffffu, s8[k], sh);
    if (lane == 0) {
#pragma unroll
        for (int k = 0; k < 8; k++) wsum[w][k] = s8[k];
    }
    __syncthreads();
    if (tid < 8) {
        float acc = 0.f;
#pragma unroll
        for (int ww = 0; ww < 8; ww++) acc += wsum[ww][tid];
        g_part[blockIdx.x * 8 + tid] = acc;
        __threadfence();
    }
    __syncthreads();

    // ---- Arrival; last block computes norm params ----
    if (tid == 0) {
        int pos = atomicAdd(&g_arrive, 1);
        shLast = ((pos % nb) == nb - 1);
    }
    __syncthreads();

    if (shLast) {
        __threadfence();
        int k = tid & 7;
        int slice = tid >> 3;
        double acc = 0.0;
        for (int b = slice; b < nb; b += 32)
            acc += (double)g_part[b * 8 + k];
        U.ru.red[k][slice] = acc;
        __syncthreads();
        if (tid < 8) {
            double t = 0.0;
#pragma unroll
            for (int i = 0; i < 32; i++) t += U.ru.red[tid][i];
            U.ru.tot[tid] = t;
        }
        __syncthreads();
        if (tid < 4) {
            double mean = U.ru.tot[tid] / (double)B;
            double var = U.ru.tot[4 + tid] / (double)B - mean * mean;
            float scale = gamma[tid] * rsqrtf((float)var + 1e-5f);
            g_norm[tid] = scale;
            g_norm[4 + tid] = beta[tid] - (float)mean * scale;
            __threadfence();
        }
        __syncthreads();
        if (tid == 0) g_norm_flag = gen + 1;
    }

    // ---- Wait for norm params, apply to register q, write out ----
    if (tid == 0) {
        while (g_norm_flag < gen + 1) __nanosleep(32);
    }
    __syncthreads();
    __threadfence();

    float sc0 = __ldcg(&g_norm[0]), sc1 = __ldcg(&g_norm[1]);
    float sc2 = __ldcg(&g_norm[2]), sc3 = __ldcg(&g_norm[3]);
    float bs0 = __ldcg(&g_norm[4]), bs1 = __ldcg(&g_norm[5]);
    float bs2 = __ldcg(&g_norm[6]), bs3 = __ldcg(&g_norm[7]);

    {
        int item = tiles0 * 256 + itemLocal;
        if (item < B) {
            float4 o;
            o.x = fmaf(q00, sc0, bs0);
            o.y = fmaf(q01, sc1, bs1);
            o.z = fmaf(q02, sc2, bs2);
            o.w = fmaf(q03, sc3, bs3);
            ((float4*)out)[item] = o;
        }
    }
    if (nt == 2) {
        int item = tiles1 * 256 + itemLocal;
        if (item < B) {
            float4 o;
            o.x = fmaf(q10, sc0, bs0);
            o.y = fmaf(q11, sc1, bs1);
            o.z = fmaf(q12, sc2, bs2);
            o.w = fmaf(q13, sc3, bs3);
            ((float4*)out)[item] = o;
        }
    }
}

// ---------------------------------------------------------------------------
extern "C" void kernel_launch(void* const* d_in, const int* in_sizes, int n_in,
                              void* d_out, int out_size)
{
    const float* x     = (const float*)d_in[0];
    const float* W     = (const float*)d_in[1];
    const float* gamma = (const float*)d_in[2];
    const float* beta  = (const float*)d_in[3];
    float* out = (float*)d_out;

    int B = in_sizes[0] / 144;
    int nChunks = (B + 255) / 256;

    // Balanced: every block gets <= 2 tiles; block 0 (setup) gets 1.
    int nb;
    if (nChunks <= NB_MAX) nb = nChunks;
    else                   nb = (nChunks + 2) / 2;   // needs nChunks <= 2*NB_MAX-2
    if (nb < 1) nb = 1;
    if (nb > NB_MAX) nb = NB_MAX;

    fused_kernel<<<nb, 256>>>(x, W, gamma, beta, out, B, nb, nChunks);
}